// round 1
// baseline (speedup 1.0000x reference)
#include <cuda_runtime.h>
#include <math.h>

#define NQc   40000
#define EDc   128
#define NVc   43520
#define HEADSc 8
#define HDc   16

typedef unsigned long long u64;

// ---------------- packed f32x2 helpers ----------------
__device__ __forceinline__ u64 dup2(float x){ u64 r; asm("mov.b64 %0,{%1,%1};":"=l"(r):"f"(x)); return r; }
__device__ __forceinline__ u64 ffma2(u64 a, u64 b, u64 c){ u64 d; asm("fma.rn.f32x2 %0,%1,%2,%3;":"=l"(d):"l"(a),"l"(b),"l"(c)); return d; }
__device__ __forceinline__ float2 unpk(u64 v){ float x,y; asm("mov.b64 {%0,%1},%2;":"=f"(x),"=f"(y):"l"(v)); return make_float2(x,y); }

// ---------------- scratch (no cudaMalloc allowed) ----------------
__device__ float g_q   [NQc*EDc];
__device__ float g_qin [NQc*EDc];
__device__ float g_v   [NVc*EDc];
__device__ float g_off [NQc*512];
__device__ float g_aw  [NQc*256];
__device__ float g_samp[NQc*EDc];
__device__ float g_t1  [NQc*EDc];
__device__ float g_t2  [NQc*EDc];
__device__ float g_c1  [NQc*128];
__device__ float g_c2  [NQc*64];
__device__ float g_c3  [NQc*48];
__device__ float g_c4  [NQc*48];
__device__ float g_wt  [49*128*128];
__device__ float g_part[320*128];
__device__ float g_scale[128];
__device__ float g_shift[128];
__device__ int   g_maxidx;

// ---------------- elementwise ----------------
__global__ void copy_k(float* __restrict__ dst, const float* __restrict__ src, int n){
    int i = blockIdx.x*256 + threadIdx.x; if (i<n) dst[i]=src[i];
}
__global__ void add_k(float* __restrict__ dst, const float* __restrict__ a, const float* __restrict__ b, int n){
    int i = blockIdx.x*256 + threadIdx.x; if (i<n) dst[i]=a[i]+b[i];
}

// ---------------- mask (max over proj_indices) ----------------
__global__ void set_min_k(){ g_maxidx = (-2147483647 - 1); }
__global__ void rmax_k(const int* __restrict__ p, int n){
    int i = blockIdx.x*256 + threadIdx.x;
    int v = (i<n)? p[i] : (-2147483647 - 1);
    #pragma unroll
    for (int o=16;o>0;o>>=1) v = max(v, __shfl_xor_sync(0xffffffffu, v, o));
    __shared__ int sm[8];
    if ((threadIdx.x&31)==0) sm[threadIdx.x>>5]=v;
    __syncthreads();
    if (threadIdx.x==0){
        int m = sm[0];
        #pragma unroll
        for (int j=1;j<8;j++) m = max(m, sm[j]);
        atomicMax(&g_maxidx, m);
    }
}
__global__ void wmask_k(const int* __restrict__ p, float* __restrict__ o, int n){
    int i = blockIdx.x*256 + threadIdx.x;
    if (i<n) o[i] = (p[i] < g_maxidx) ? 1.0f : 0.0f;
}

// ---------------- GEMM: C[M,N] = A[M,K] @ B[K,N] + bias (opt relu) ----------------
// 64x64 tile, 256 threads, 4x4 micro-tile with fma.rn.f32x2
__global__ void __launch_bounds__(256) gemm_k(
    const float* __restrict__ A, const float* __restrict__ B,
    const float* __restrict__ bias, float* __restrict__ C,
    int M, int N, int K, int relu)
{
    __shared__ float As[16][68];
    __shared__ float Bs[16][68];
    int bm = blockIdx.y<<6, bn = blockIdx.x<<6;
    int tid = threadIdx.x;
    int tx = tid & 15, ty = tid >> 4;
    u64 acc[4][2];
    #pragma unroll
    for (int i=0;i<4;i++){acc[i][0]=0ull; acc[i][1]=0ull;}
    int ra = tid>>2, ka=(tid&3)<<2;
    int rb = tid>>4, cb=(tid&15)<<2;
    for (int k0=0;k0<K;k0+=16){
        int am = bm+ra;
        float4 av = make_float4(0.f,0.f,0.f,0.f);
        if (am < M) av = *(const float4*)&A[(size_t)am*K + k0+ka];
        As[ka  ][ra]=av.x; As[ka+1][ra]=av.y; As[ka+2][ra]=av.z; As[ka+3][ra]=av.w;
        float4 bv = *(const float4*)&B[(size_t)(k0+rb)*N + bn+cb];
        *(float4*)&Bs[rb][cb] = bv;
        __syncthreads();
        #pragma unroll
        for (int kk=0;kk<16;kk++){
            float4 a4 = *(const float4*)&As[kk][ty<<2];
            u64 b01 = *(const u64*)&Bs[kk][tx<<2];
            u64 b23 = *(const u64*)&Bs[kk][(tx<<2)+2];
            u64 a0=dup2(a4.x),a1=dup2(a4.y),a2=dup2(a4.z),a3=dup2(a4.w);
            acc[0][0]=ffma2(a0,b01,acc[0][0]); acc[0][1]=ffma2(a0,b23,acc[0][1]);
            acc[1][0]=ffma2(a1,b01,acc[1][0]); acc[1][1]=ffma2(a1,b23,acc[1][1]);
            acc[2][0]=ffma2(a2,b01,acc[2][0]); acc[2][1]=ffma2(a2,b23,acc[2][1]);
            acc[3][0]=ffma2(a3,b01,acc[3][0]); acc[3][1]=ffma2(a3,b23,acc[3][1]);
        }
        __syncthreads();
    }
    #pragma unroll
    for (int i=0;i<4;i++){
        int m = bm + (ty<<2) + i;
        if (m>=M) continue;
        #pragma unroll
        for (int j2=0;j2<2;j2++){
            float2 p = unpk(acc[i][j2]);
            int n = bn + (tx<<2) + (j2<<1);
            float o0 = p.x + bias[n], o1 = p.y + bias[n+1];
            if (relu){ o0=fmaxf(o0,0.f); o1=fmaxf(o1,0.f); }
            C[(size_t)m*N+n]=o0; C[(size_t)m*N+n+1]=o1;
        }
    }
}

// ---------------- softmax over 32 (per query,head) ----------------
__global__ void softmax32_k(float* __restrict__ a){
    int warp = threadIdx.x>>5, lane = threadIdx.x&31;
    int row = blockIdx.x*8 + warp;
    float v = a[(size_t)row*32 + lane];
    float m = v;
    #pragma unroll
    for (int o=16;o>0;o>>=1) m = fmaxf(m, __shfl_xor_sync(0xffffffffu, m, o));
    float e = expf(v - m);
    float s = e;
    #pragma unroll
    for (int o=16;o>0;o>>=1) s += __shfl_xor_sync(0xffffffffu, s, o);
    a[(size_t)row*32 + lane] = e / s;
}

// ---------------- deformable bilinear sampling ----------------
__global__ void __launch_bounds__(256) sample_k(
    const float* __restrict__ v, const float* __restrict__ off,
    const float* __restrict__ aw, float* __restrict__ samp)
{
    int t = blockIdx.x*256 + threadIdx.x;
    if (t >= NQc*EDc) return;
    int q = t >> 7, r = t & 127, h = r >> 4, d = r & 15;
    float refx = ((float)(q % 200) + 0.5f) * (1.f/200.f);
    float refy = ((float)(q / 200) + 0.5f) * (1.f/200.f);
    const float* op = off + (size_t)(q*8 + h)*64;
    const float* ap = aw  + (size_t)(q*8 + h)*32;
    const int ch = h*16 + d;
    const int Ws_[4]={256,128,64,32};
    const int Hs_[4]={128,64,32,16};
    const int Bs_[4]={0,32768,40960,43008};
    float acc = 0.f;
    #pragma unroll
    for (int l=0;l<4;l++){
        int W=Ws_[l], Hh=Hs_[l], base=Bs_[l];
        float fW=(float)W, fH=(float)Hh;
        #pragma unroll
        for (int p=0;p<8;p++){
            float ox = op[l*16 + p*2];
            float oy = op[l*16 + p*2 + 1];
            float x = refx*fW + ox - 0.5f;
            float y = refy*fH + oy - 0.5f;
            float x0f = floorf(x), y0f = floorf(y);
            int x0 = (int)x0f, y0 = (int)y0f;
            float fx = x - x0f, fy = y - y0f;
            float a = ap[l*8 + p];
            float s = 0.f;
            if (y0 >= 0 && y0 < Hh){
                int rowb = base + y0*W;
                if (x0   >= 0 && x0   < W) s += (1.f-fx)*(1.f-fy) * v[(size_t)(rowb+x0  )*128 + ch];
                if (x0+1 >= 0 && x0+1 < W) s += fx*(1.f-fy)       * v[(size_t)(rowb+x0+1)*128 + ch];
            }
            int y1 = y0+1;
            if (y1 >= 0 && y1 < Hh){
                int rowb = base + y1*W;
                if (x0   >= 0 && x0   < W) s += (1.f-fx)*fy * v[(size_t)(rowb+x0  )*128 + ch];
                if (x0+1 >= 0 && x0+1 < W) s += fx*fy       * v[(size_t)(rowb+x0+1)*128 + ch];
            }
            acc += a * s;
        }
    }
    samp[(size_t)q*128 + h*16 + d] = acc;
}

// ---------------- residual + LayerNorm (in-place on q) ----------------
__global__ void ln_res_k(float* __restrict__ q, const float* __restrict__ r,
                         const float* __restrict__ g, const float* __restrict__ b)
{
    int row = blockIdx.x, c = threadIdx.x;
    size_t idx = (size_t)row*128 + c;
    float x = q[idx] + r[idx];
    __shared__ float sm[4];
    float s = x;
    #pragma unroll
    for (int o=16;o>0;o>>=1) s += __shfl_xor_sync(0xffffffffu, s, o);
    if ((c&31)==0) sm[c>>5]=s;
    __syncthreads();
    float mean = (sm[0]+sm[1]+sm[2]+sm[3]) * (1.f/128.f);
    __syncthreads();
    float dlt = x - mean;
    float s2 = dlt*dlt;
    #pragma unroll
    for (int o=16;o>0;o>>=1) s2 += __shfl_xor_sync(0xffffffffu, s2, o);
    if ((c&31)==0) sm[c>>5]=s2;
    __syncthreads();
    float var = (sm[0]+sm[1]+sm[2]+sm[3]) * (1.f/128.f);
    q[idx] = dlt * rsqrtf(var + 1e-5f) * g[c] + b[c];
}

// ---------------- weight transpose: OIHW -> [tap][IC][OC] ----------------
__global__ void transpose_w_k(const float* __restrict__ w, float* __restrict__ wt,
                              int OC, int IC, int KS, int total)
{
    int i = blockIdx.x*256 + threadIdx.x;
    if (i >= total) return;
    int ksks = KS*KS;
    int oc = i / (IC*ksks);
    int rem = i - oc*IC*ksks;
    int ic = rem / ksks;
    int tap = rem - ic*ksks;
    wt[(size_t)tap*IC*OC + (size_t)ic*OC + oc] = w[i];
}

// ---------------- NHWC direct conv as tap-looped implicit GEMM ----------------
// in: [40000][IC], wt: [KS*KS][IC][OC], out: [40000][OC], H=W=200
__global__ void __launch_bounds__(256) conv_k(
    const float* __restrict__ in, const float* __restrict__ wt,
    float* __restrict__ out, int IC, int OC, int KS, int pad)
{
    __shared__ float As[16][68];
    __shared__ float Bs[16][68];
    __shared__ int srow[64];
    int bm = blockIdx.y<<6, bn = blockIdx.x<<6;
    int tid = threadIdx.x;
    int tx = tid & 15, ty = tid >> 4;
    u64 acc[4][2];
    #pragma unroll
    for (int i=0;i<4;i++){acc[i][0]=0ull; acc[i][1]=0ull;}
    int ra = tid>>2, ka=(tid&3)<<2;
    int rb = tid>>4, cb=(tid&15)<<2;
    int ksks = KS*KS;
    for (int tap=0; tap<ksks; tap++){
        int dy = tap/KS - pad, dx = tap%KS - pad;
        if (tid < 64){
            int p = bm + tid;
            int py = p / 200, px = p - py*200;
            int sy = py + dy, sx = px + dx;
            srow[tid] = (sy>=0 && sy<200 && sx>=0 && sx<200) ? (sy*200+sx)*IC : -1;
        }
        __syncthreads();
        const float* wtap = wt + (size_t)tap*IC*OC;
        for (int k0=0;k0<IC;k0+=16){
            int rr = srow[ra];
            float4 av = make_float4(0.f,0.f,0.f,0.f);
            if (rr >= 0) av = *(const float4*)&in[rr + k0 + ka];
            As[ka  ][ra]=av.x; As[ka+1][ra]=av.y; As[ka+2][ra]=av.z; As[ka+3][ra]=av.w;
            float4 bv = make_float4(0.f,0.f,0.f,0.f);
            if (bn + cb + 4 <= OC) bv = *(const float4*)&wtap[(size_t)(k0+rb)*OC + bn + cb];
            *(float4*)&Bs[rb][cb] = bv;
            __syncthreads();
            #pragma unroll
            for (int kk=0;kk<16;kk++){
                float4 a4 = *(const float4*)&As[kk][ty<<2];
                u64 b01 = *(const u64*)&Bs[kk][tx<<2];
                u64 b23 = *(const u64*)&Bs[kk][(tx<<2)+2];
                u64 a0=dup2(a4.x),a1=dup2(a4.y),a2=dup2(a4.z),a3=dup2(a4.w);
                acc[0][0]=ffma2(a0,b01,acc[0][0]); acc[0][1]=ffma2(a0,b23,acc[0][1]);
                acc[1][0]=ffma2(a1,b01,acc[1][0]); acc[1][1]=ffma2(a1,b23,acc[1][1]);
                acc[2][0]=ffma2(a2,b01,acc[2][0]); acc[2][1]=ffma2(a2,b23,acc[2][1]);
                acc[3][0]=ffma2(a3,b01,acc[3][0]); acc[3][1]=ffma2(a3,b23,acc[3][1]);
            }
            __syncthreads();
        }
    }
    #pragma unroll
    for (int i=0;i<4;i++){
        int p = bm + (ty<<2) + i;
        #pragma unroll
        for (int j2=0;j2<2;j2++){
            float2 pv = unpk(acc[i][j2]);
            int n = bn + (tx<<2) + (j2<<1);
            if (n   < OC) out[(size_t)p*OC + n  ] = pv.x;
            if (n+1 < OC) out[(size_t)p*OC + n+1] = pv.y;
        }
    }
}

// ---------------- BN stats (deterministic 2-stage) + apply ----------------
__global__ void bn_partial_k(const float* __restrict__ x, int C, float* __restrict__ part){
    int c = threadIdx.x, b = blockIdx.x;
    int p0 = b*250;
    float s=0.f, q=0.f;
    for (int p=0;p<250;p++){
        float v = x[(size_t)(p0+p)*C + c];
        s += v; q += v*v;
    }
    part[(size_t)b*C + c] = s;
    part[(size_t)(160+b)*C + c] = q;
}
__global__ void bn_finish_k(const float* __restrict__ part, const float* __restrict__ g,
                            const float* __restrict__ bb, float* __restrict__ scale,
                            float* __restrict__ shift, int C)
{
    int c = threadIdx.x;
    float s=0.f, q=0.f;
    for (int b=0;b<160;b++){ s += part[(size_t)b*C + c]; q += part[(size_t)(160+b)*C + c]; }
    float m = s * (1.f/40000.f);
    float v = q * (1.f/40000.f) - m*m;
    float sc = g[c] * rsqrtf(v + 1e-5f);
    scale[c] = sc;
    shift[c] = bb[c] - m*sc;
}
__global__ void bn_apply_k(float* __restrict__ x, const float* __restrict__ scale,
                           const float* __restrict__ shift, int C, int total)
{
    int i = blockIdx.x*256 + threadIdx.x;
    if (i >= total) return;
    int c = i % C;
    x[i] = fmaxf(x[i]*scale[c] + shift[c], 0.f);
}

// ---------------- final 1x1 conv (48 -> 21), NCHW output ----------------
__global__ void conv5_k(const float* __restrict__ h4, const float* __restrict__ w,
                        const float* __restrict__ b, float* __restrict__ out)
{
    int t = blockIdx.x*256 + threadIdx.x;
    int p = t >> 5, cls = t & 31;
    if (p >= 40000 || cls >= 21) return;
    const float* hr = h4 + (size_t)p*48;
    const float* wr = w + cls*48;
    float s = b[cls];
    #pragma unroll
    for (int c=0;c<48;c++) s += hr[c]*wr[c];
    out[(size_t)cls*40000 + p] = s;
}

// ==================================================================
extern "C" void kernel_launch(void* const* d_in, const int* in_sizes, int n_in,
                              void* d_out, int out_size)
{
    const float* value = (const float*)d_in[0];
    const float* bq    = (const float*)d_in[1];
    const float* bpos  = (const float*)d_in[2];
    const int*   proj  = (const int*)  d_in[3];
    const float* Wv    = (const float*)d_in[4];
    const float* bv    = (const float*)d_in[5];
    const float* Woff  = (const float*)d_in[6];
    const float* boff  = (const float*)d_in[7];
    const float* Wattn = (const float*)d_in[8];
    const float* battn = (const float*)d_in[9];
    const float* Wout  = (const float*)d_in[10];
    const float* bout  = (const float*)d_in[11];
    const float* Wf1   = (const float*)d_in[12];
    const float* bf1   = (const float*)d_in[13];
    const float* Wf2   = (const float*)d_in[14];
    const float* bf2   = (const float*)d_in[15];
    const float* lng   = (const float*)d_in[16];
    const float* lnb   = (const float*)d_in[17];
    const float* cw1   = (const float*)d_in[18];
    const float* g1    = (const float*)d_in[19];
    const float* b1    = (const float*)d_in[20];
    const float* cw2   = (const float*)d_in[21];
    const float* g2    = (const float*)d_in[22];
    const float* b2    = (const float*)d_in[23];
    const float* cw3   = (const float*)d_in[24];
    const float* g3    = (const float*)d_in[25];
    const float* b3    = (const float*)d_in[26];
    const float* cw4   = (const float*)d_in[27];
    const float* g4    = (const float*)d_in[28];
    const float* b4    = (const float*)d_in[29];
    const float* objw  = (const float*)d_in[30];
    const float* objb  = (const float*)d_in[31];
    float* out = (float*)d_out;

    float *p_q,*p_qin,*p_v,*p_off,*p_aw,*p_samp,*p_t1,*p_t2;
    float *p_c1,*p_c2,*p_c3,*p_c4,*p_wt,*p_part,*p_scale,*p_shift;
    cudaGetSymbolAddress((void**)&p_q,    g_q);
    cudaGetSymbolAddress((void**)&p_qin,  g_qin);
    cudaGetSymbolAddress((void**)&p_v,    g_v);
    cudaGetSymbolAddress((void**)&p_off,  g_off);
    cudaGetSymbolAddress((void**)&p_aw,   g_aw);
    cudaGetSymbolAddress((void**)&p_samp, g_samp);
    cudaGetSymbolAddress((void**)&p_t1,   g_t1);
    cudaGetSymbolAddress((void**)&p_t2,   g_t2);
    cudaGetSymbolAddress((void**)&p_c1,   g_c1);
    cudaGetSymbolAddress((void**)&p_c2,   g_c2);
    cudaGetSymbolAddress((void**)&p_c3,   g_c3);
    cudaGetSymbolAddress((void**)&p_c4,   g_c4);
    cudaGetSymbolAddress((void**)&p_wt,   g_wt);
    cudaGetSymbolAddress((void**)&p_part, g_part);
    cudaGetSymbolAddress((void**)&p_scale,g_scale);
    cudaGetSymbolAddress((void**)&p_shift,g_shift);

    const int NE = NQc*EDc;            // 5,120,000
    const int EB = (NE+255)/256;       // 20000

    // ---- observed_masks ----
    set_min_k<<<1,1>>>();
    rmax_k<<<(40000+255)/256,256>>>(proj, 40000);
    if (out_size >= 880000)
        wmask_k<<<(40000+255)/256,256>>>(proj, out + 840000, 40000);

    // ---- encoder ----
    copy_k<<<EB,256>>>(p_q, bq, NE);
    for (int i=0;i<2;i++){
        add_k<<<EB,256>>>(p_qin, p_q, bpos, NE);
        gemm_k<<<dim3(2,680),256>>>(value, Wv + (size_t)i*EDc*EDc, bv + i*EDc, p_v, NVc, EDc, EDc, 0);
        gemm_k<<<dim3(8,625),256>>>(p_qin, Woff + (size_t)i*EDc*512, boff + i*512, p_off, NQc, 512, EDc, 0);
        gemm_k<<<dim3(4,625),256>>>(p_qin, Wattn + (size_t)i*EDc*256, battn + i*256, p_aw, NQc, 256, EDc, 0);
        softmax32_k<<<40000,256>>>(p_aw);
        sample_k<<<EB,256>>>(p_v, p_off, p_aw, p_samp);
        gemm_k<<<dim3(2,625),256>>>(p_samp, Wout + (size_t)i*EDc*EDc, bout + i*EDc, p_t1, NQc, EDc, EDc, 0);
        ln_res_k<<<40000,128>>>(p_q, p_t1, lng + (i*2+0)*EDc, lnb + (i*2+0)*EDc);
        gemm_k<<<dim3(2,625),256>>>(p_q, Wf1 + (size_t)i*EDc*EDc, bf1 + i*EDc, p_t1, NQc, EDc, EDc, 1);
        gemm_k<<<dim3(2,625),256>>>(p_t1, Wf2 + (size_t)i*EDc*EDc, bf2 + i*EDc, p_t2, NQc, EDc, EDc, 0);
        ln_res_k<<<40000,128>>>(p_q, p_t2, lng + (i*2+1)*EDc, lnb + (i*2+1)*EDc);
    }

    // ---- conv head (NHWC) ----
    // conv1: 128->128, 7x7, pad 3
    transpose_w_k<<<(49*128*128+255)/256,256>>>(cw1, p_wt, 128, 128, 7, 49*128*128);
    conv_k<<<dim3(2,625),256>>>(p_q, p_wt, p_c1, 128, 128, 7, 3);
    bn_partial_k<<<160,128>>>(p_c1, 128, p_part);
    bn_finish_k<<<1,128>>>(p_part, g1, b1, p_scale, p_shift, 128);
    bn_apply_k<<<(40000*128)/256,256>>>(p_c1, p_scale, p_shift, 128, 40000*128);

    // conv2: 128->64, 3x3, pad 1
    transpose_w_k<<<(9*128*64+255)/256,256>>>(cw2, p_wt, 64, 128, 3, 9*128*64);
    conv_k<<<dim3(1,625),256>>>(p_c1, p_wt, p_c2, 128, 64, 3, 1);
    bn_partial_k<<<160,64>>>(p_c2, 64, p_part);
    bn_finish_k<<<1,64>>>(p_part, g2, b2, p_scale, p_shift, 64);
    bn_apply_k<<<(40000*64)/256,256>>>(p_c2, p_scale, p_shift, 64, 40000*64);

    // conv3: 64->48, 3x3, pad 1
    transpose_w_k<<<(9*64*48+255)/256,256>>>(cw3, p_wt, 48, 64, 3, 9*64*48);
    conv_k<<<dim3(1,625),256>>>(p_c2, p_wt, p_c3, 64, 48, 3, 1);
    bn_partial_k<<<160,48>>>(p_c3, 48, p_part);
    bn_finish_k<<<1,48>>>(p_part, g3, b3, p_scale, p_shift, 48);
    bn_apply_k<<<(40000*48)/256,256>>>(p_c3, p_scale, p_shift, 48, 40000*48);

    // conv4: 48->48, 3x3, pad 1
    transpose_w_k<<<(9*48*48+255)/256,256>>>(cw4, p_wt, 48, 48, 3, 9*48*48);
    conv_k<<<dim3(1,625),256>>>(p_c3, p_wt, p_c4, 48, 48, 3, 1);
    bn_partial_k<<<160,48>>>(p_c4, 48, p_part);
    bn_finish_k<<<1,48>>>(p_part, g4, b4, p_scale, p_shift, 48);
    bn_apply_k<<<(40000*48)/256,256>>>(p_c4, p_scale, p_shift, 48, 40000*48);

    // final 1x1 conv -> semmap
    conv5_k<<<(40000*32)/256,256>>>(p_c4, objw, objb, out);
}